// round 14
// baseline (speedup 1.0000x reference)
#include <cuda_runtime.h>
#include <cuda_bf16.h>

#define Bb 256
#define Tt 240
#define Cc 512
#define Kk 64
#define NCn 4
#define TB 16
#define NCHUNK 15
#define NT 1024
#define XS 516            // raw x row stride (f32)
#define CPB 520           // conv bf16 row stride
#define AS 68             // a_s row stride (f32)
#define VS 513            // vlad row stride
#define XBUFW (TB*XS)     // 8256 floats per buffer

// smem byte offsets
#define CONV_OFF 0                 // bf16 [64][520] = 66560
#define XRAW_OFF 66560             // f32 [3][16][516] = 99072 -> 165632
#define RED_OFF  165632            // f32 [4][16][65] = 16640 -> 182272
#define A_OFF    182272            // f32 [16][68] = 4352 -> 186624
#define ASUM_OFF 186624
#define KN_OFF   186880
#define MISC_OFF 187136
#define WRED_OFF 187200
#define SMEM_TOTAL 187264

typedef unsigned int uint;

__device__ __forceinline__ void cp_async16(void* d,const void* s){uint a=(uint)__cvta_generic_to_shared(d);asm volatile("cp.async.cg.shared.global [%0],[%1],16;"::"r"(a),"l"(s));}
__device__ __forceinline__ uint bfp(float x0,float x1){uint r;asm("cvt.rn.bf16x2.f32 %0,%1,%2;":"=r"(r):"f"(x1),"f"(x0));return r;}
__device__ __forceinline__ void mma16(float* c,uint a0,uint a1,uint a2,uint a3,uint b0,uint b1){
    asm("mma.sync.aligned.m16n8k16.row.col.f32.bf16.bf16.f32 {%0,%1,%2,%3},{%4,%5,%6,%7},{%8,%9},{%0,%1,%2,%3};"
        : "+f"(c[0]),"+f"(c[1]),"+f"(c[2]),"+f"(c[3])
        : "r"(a0),"r"(a1),"r"(a2),"r"(a3),"r"(b0),"r"(b1));}

// logits x[16,512] @ conv^T -> red[4][16][65]
__device__ __forceinline__ void phase2(const float* xb, float* red, const __nv_bfloat16* convb, int warp, int lane){
    const int grp=lane>>2, tig=lane&3;
    const int kt=warp>>3, cg=warp&7;
    float p0[4]={0.f,0.f,0.f,0.f}, p1[4]={0.f,0.f,0.f,0.f};
    const __nv_bfloat16* brow=convb+(cg*8+grp)*CPB+kt*128;
    #pragma unroll
    for(int s=0;s<4;s++){
        int c0=kt*128+s*16+2*tig;
        int c1=c0+64;   // s+4
        uint a0=bfp(xb[grp*XS+c0],      xb[grp*XS+c0+1]);
        uint a1=bfp(xb[(grp+8)*XS+c0],  xb[(grp+8)*XS+c0+1]);
        uint a2=bfp(xb[grp*XS+c0+8],    xb[grp*XS+c0+9]);
        uint a3=bfp(xb[(grp+8)*XS+c0+8],xb[(grp+8)*XS+c0+9]);
        uint b0=*(const uint*)(brow+s*16+2*tig);
        uint b1=*(const uint*)(brow+s*16+2*tig+8);
        mma16(p0,a0,a1,a2,a3,b0,b1);
        uint d0=bfp(xb[grp*XS+c1],      xb[grp*XS+c1+1]);
        uint d1=bfp(xb[(grp+8)*XS+c1],  xb[(grp+8)*XS+c1+1]);
        uint d2=bfp(xb[grp*XS+c1+8],    xb[grp*XS+c1+9]);
        uint d3=bfp(xb[(grp+8)*XS+c1+8],xb[(grp+8)*XS+c1+9]);
        uint e0=*(const uint*)(brow+(s+4)*16+2*tig);
        uint e1=*(const uint*)(brow+(s+4)*16+2*tig+8);
        mma16(p1,d0,d1,d2,d3,e0,e1);
    }
    int ko=cg*8+2*tig;
    red[kt*1040+grp*65+ko]      =p0[0]+p1[0];
    red[kt*1040+grp*65+ko+1]    =p0[1]+p1[1];
    red[kt*1040+(grp+8)*65+ko]  =p0[2]+p1[2];
    red[kt*1040+(grp+8)*65+ko+1]=p0[3]+p1[3];
}

__global__ void __launch_bounds__(NT,1)
netvlad_kernel(const float* __restrict__ gin, const float* __restrict__ candA,
               const float* __restrict__ candB, const float* __restrict__ gfcw,
               const float* __restrict__ gfcb, float* __restrict__ gout)
{
    extern __shared__ __align__(1024) char smraw[];
    __nv_bfloat16* convb=(__nv_bfloat16*)(smraw+CONV_OFF);
    float* red  =(float*)(smraw+RED_OFF);
    float* a_s  =(float*)(smraw+A_OFF);
    float* asum_s=(float*)(smraw+ASUM_OFF);
    float* knorm=(float*)(smraw+KN_OFF);
    float* misc =(float*)(smraw+MISC_OFF);
    float* wred =(float*)(smraw+WRED_OFF);
    const int tid=threadIdx.x, lane=tid&31, warp=tid>>5, b=blockIdx.x;

    if (warp==0){
        float s=fabsf(candA[lane])+fabsf(candA[lane+32])+fabsf(candA[lane+64])+fabsf(candA[lane+96]);
        #pragma unroll
        for(int o=16;o;o>>=1) s+=__shfl_xor_sync(0xffffffffu,s,o);
        if(lane==0) misc[7]=s;
    }
    if (tid<Kk){asum_s[tid]=0.f; knorm[tid]=0.f;}
    if (tid<8) wred[tid]=0.f;
    __syncthreads();
    const bool aIsConv=(misc[7]<25.6f);
    const float* gconv=aIsConv?candA:candB;
    const float* gcent=aIsConv?candB:candA;
    __syncthreads();

    for(int idx=tid;idx<Kk*Cc;idx+=NT){int k=idx>>9,c=idx&511;convb[k*CPB+c]=__float2bfloat16(gconv[idx]);}

    const float* inb=gin+(size_t)b*(Tt*Cc);
    const int lrow=tid>>6, lcol=(tid&63)*8;
    float* xbuf=(float*)(smraw+XRAW_OFF);

    // prologue: cp chunk0 -> buf0, chunk1 -> buf1
    {
        float* d0=xbuf+lrow*XS+lcol;
        const float* s0=inb+lrow*Cc+lcol;
        cp_async16(d0,s0); cp_async16(d0+4,s0+4);
        asm volatile("cp.async.commit_group;");
        float* d1=xbuf+XBUFW+lrow*XS+lcol;
        const float* s1=inb+TB*Cc+lrow*Cc+lcol;
        cp_async16(d1,s1); cp_async16(d1+4,s1+4);
        asm volatile("cp.async.commit_group;");
        asm volatile("cp.async.wait_group 1;");   // buf0 ready
    }
    const int grp=lane>>2, tig=lane&3;
    const int kt=warp>>3, cg=warp&7;
    float acc[8][4];
    #pragma unroll
    for(int i=0;i<8;i++){acc[i][0]=0.f;acc[i][1]=0.f;acc[i][2]=0.f;acc[i][3]=0.f;}
    __syncthreads();
    phase2(xbuf, red, convb, warp, lane);   // logits(0)
    __syncthreads();

    for (int ch=0; ch<NCHUNK; ch++){
        float* xb=xbuf+(ch%3)*XBUFW;
        // ---- region S: softmax(ch) on warps 0-15; all warps drain cp group ----
        if (warp<16){
            const int t=warp;
            const float* rp=xb+t*XS+4*lane;
            float4 q0=*(const float4*)rp,q1=*(const float4*)(rp+128),q2=*(const float4*)(rp+256),q3=*(const float4*)(rp+384);
            float ss=q0.x*q0.x+q0.y*q0.y+q0.z*q0.z+q0.w*q0.w+q1.x*q1.x+q1.y*q1.y+q1.z*q1.z+q1.w*q1.w
                    +q2.x*q2.x+q2.y*q2.y+q2.z*q2.z+q2.w*q2.w+q3.x*q3.x+q3.y*q3.y+q3.z*q3.z+q3.w*q3.w;
            #pragma unroll
            for(int o=16;o;o>>=1) ss+=__shfl_xor_sync(0xffffffffu,ss,o);
            float inv=1.0f/fmaxf(sqrtf(ss),1e-12f);
            float lg0=0.f,lg1=0.f;
            #pragma unroll
            for(int s=0;s<4;s++){lg0+=red[s*1040+t*65+lane];lg1+=red[s*1040+t*65+lane+32];}
            lg0*=inv; lg1*=inv;
            float m=fmaxf(lg0,lg1);
            #pragma unroll
            for(int o=16;o;o>>=1) m=fmaxf(m,__shfl_xor_sync(0xffffffffu,m,o));
            float e0=__expf(lg0-m),e1=__expf(lg1-m),s2=e0+e1;
            #pragma unroll
            for(int o=16;o;o>>=1) s2+=__shfl_xor_sync(0xffffffffu,s2,o);
            float a0=e0/s2,a1=e1/s2;
            a_s[t*AS+lane]=a0*inv; a_s[t*AS+lane+32]=a1*inv;   // a' = a/||x||
            atomicAdd(&asum_s[lane],a0); atomicAdd(&asum_s[lane+32],a1);
        }
        asm volatile("cp.async.wait_group 0;");   // buf(ch+1) landed (this thread's part)
        __syncthreads();                          // all threads' parts visible
        // ---- region M: phase2(ch+1) + VLAD(ch) + issue cp(ch+2) ----
        if (ch+1<NCHUNK) phase2(xbuf+((ch+1)%3)*XBUFW, red, convb, warp, lane);
        {
            const int r=kt*16+grp;
            uint fa0=bfp(a_s[(2*tig)*AS+r],     a_s[(2*tig+1)*AS+r]);
            uint fa1=bfp(a_s[(2*tig)*AS+r+8],   a_s[(2*tig+1)*AS+r+8]);
            uint fa2=bfp(a_s[(2*tig+8)*AS+r],   a_s[(2*tig+9)*AS+r]);
            uint fa3=bfp(a_s[(2*tig+8)*AS+r+8], a_s[(2*tig+9)*AS+r+8]);
            const int cb=cg*64+grp;
            #pragma unroll
            for(int i=0;i<8;i++){
                int c=cb+i*8;
                uint fb0=bfp(xb[(2*tig)*XS+c],   xb[(2*tig+1)*XS+c]);
                uint fb1=bfp(xb[(2*tig+8)*XS+c], xb[(2*tig+9)*XS+c]);
                mma16(acc[i],fa0,fa1,fa2,fa3,fb0,fb1);
            }
        }
        if (ch+2<NCHUNK){
            float* d=xbuf+((ch+2)%3)*XBUFW+lrow*XS+lcol;
            const float* s=inb+(ch+2)*(TB*Cc)+lrow*Cc+lcol;
            cp_async16(d,s); cp_async16(d+4,s+4);
            asm volatile("cp.async.commit_group;");
        }
        __syncthreads();
    }

    // ===== epilogue (verified) =====
    float* vlad=(float*)smraw;   // overlay conv+xraw, stride VS
    {
        int r0=kt*16+grp, r1=r0+8;
        float a0s=asum_s[r0], a1s=asum_s[r1];
        float pk0=0.f, pk1=0.f;
        #pragma unroll
        for(int i=0;i<8;i++){
            int c=cg*64+i*8+2*tig;
            float2 c0=*(const float2*)(gcent+(size_t)r0*Cc+c);
            float2 c1=*(const float2*)(gcent+(size_t)r1*Cc+c);
            float v00=acc[i][0]-a0s*c0.x, v01=acc[i][1]-a0s*c0.y;
            float v10=acc[i][2]-a1s*c1.x, v11=acc[i][3]-a1s*c1.y;
            vlad[r0*VS+c]=v00; vlad[r0*VS+c+1]=v01;
            vlad[r1*VS+c]=v10; vlad[r1*VS+c+1]=v11;
            pk0+=v00*v00+v01*v01; pk1+=v10*v10+v11*v11;
        }
        pk0+=__shfl_xor_sync(0xffffffffu,pk0,1); pk0+=__shfl_xor_sync(0xffffffffu,pk0,2);
        pk1+=__shfl_xor_sync(0xffffffffu,pk1,1); pk1+=__shfl_xor_sync(0xffffffffu,pk1,2);
        if(tig==0){atomicAdd(&knorm[r0],pk0); atomicAdd(&knorm[r1],pk1);}
    }
    __syncthreads();
    if (warp==0){
        float c0=0.f;
        #pragma unroll
        for(int r=0;r<2;r++){float nn=knorm[lane+32*r];float iv=1.0f/fmaxf(sqrtf(nn),1e-12f);c0+=nn*iv*iv;}
        #pragma unroll
        for(int o=16;o;o>>=1) c0+=__shfl_xor_sync(0xffffffffu,c0,o);
        if(lane==0) misc[0]=1.0f/fmaxf(sqrtf(c0),1e-12f);
    }
    __syncthreads();
    {
        float invtot=misc[0];
        int k=tid>>4;
        float sc=(1.0f/fmaxf(sqrtf(knorm[k]),1e-12f))*invtot;
        int off=(tid&15)*32;
        float fo[NCn]={0.f,0.f,0.f,0.f};
        #pragma unroll 4
        for(int o=0;o<32;o++){
            int j=off+((o+lane)&31);
            float v=vlad[k*VS+j]*sc;
            #pragma unroll
            for(int n=0;n<NCn;n++) fo[n]+=v*gfcw[(size_t)n*(Kk*Cc)+k*Cc+j];
        }
        #pragma unroll
        for(int n=0;n<NCn;n++){
            float v=fo[n];
            #pragma unroll
            for(int o=16;o;o>>=1) v+=__shfl_xor_sync(0xffffffffu,v,o);
            if(lane==0) atomicAdd(&wred[n],v);
        }
    }
    __syncthreads();
    if (tid<NCn){
        float z=gfcb[tid]+wred[tid];
        gout[b*NCn+tid]=1.0f/(1.0f+__expf(-z));
    }
}

extern "C" void kernel_launch(void* const* d_in, const int* in_sizes, int n_in,
                              void* d_out, int out_size) {
    const float *gin=nullptr,*gfcw=nullptr,*gfcb=nullptr,*cand[2]={nullptr,nullptr};
    if (n_in>=5){
        int used[32]; for(int i=0;i<n_in&&i<32;i++) used[i]=0;
        int imax=-1; for(int i=0;i<n_in&&i<32;i++) if(!used[i]&&(imax<0||in_sizes[i]>in_sizes[imax])) imax=i;
        used[imax]=1; gin=(const float*)d_in[imax];
        int imin=-1; for(int i=0;i<n_in&&i<32;i++) if(!used[i]&&(imin<0||in_sizes[i]<in_sizes[imin])) imin=i;
        used[imin]=1; gfcb=(const float*)d_in[imin];
        int iw=-1; for(int i=0;i<n_in&&i<32;i++) if(!used[i]&&(iw<0||in_sizes[i]>in_sizes[iw])) iw=i;
        used[iw]=1; gfcw=(const float*)d_in[iw];
        int nc=0; for(int i=0;i<n_in&&i<32&&nc<2;i++) if(!used[i]){cand[nc++]=(const float*)d_in[i];used[i]=1;}
        if (nc<2 || in_sizes[imax]==in_sizes[iw] || in_sizes[iw]<=in_sizes[imin]){
            gin=(const float*)d_in[0]; cand[0]=(const float*)d_in[1]; cand[1]=(const float*)d_in[2];
            gfcw=(const float*)d_in[3]; gfcb=(const float*)d_in[4];
        }
    }
    cudaFuncSetAttribute(netvlad_kernel, cudaFuncAttributeMaxDynamicSharedMemorySize, SMEM_TOTAL);
    netvlad_kernel<<<Bb, NT, SMEM_TOTAL>>>(gin, cand[0], cand[1], gfcw, gfcb, (float*)d_out);
}

// round 15
// speedup vs baseline: 1.1552x; 1.1552x over previous
#include <cuda_runtime.h>
#include <cuda_bf16.h>

#define Bb 256
#define Tt 240
#define Cc 512
#define Kk 64
#define NCn 4
#define TB 16
#define NCHUNK 15
#define NT 1024
#define XS 520            // f32 x row stride (words): phase2 LDS.64 conflict-free
#define XTW 12            // xT row stride (words), 24 bf16: VLAD conflict-free
#define CPB 520           // conv bf16 row stride
#define VS 513            // vlad row stride

// smem byte offsets
#define XF_OFF   0                  // f32 [2][16][520] = 66560
#define XT_OFF   66560              // bf16 xT [2][512][24] = 49152 -> 115712
#define CONV_OFF 115712             // bf16 [64][520] = 66560 -> 182272
#define REDB_OFF 182272             // bf16 [4][16][72] = 9216 -> 191488
#define AT_OFF   191488             // bf16 [64][24] = 3072 -> 194560
#define INV_OFF  194560             // f32[16]
#define ASUM_OFF 194688             // f32[64]
#define KN_OFF   194944             // f32[64]
#define MISC_OFF 195200             // f32[8]
#define WRED_OFF 195232             // f32[8]
#define SMEM_TOTAL 195264

typedef unsigned int uint;

__device__ __forceinline__ void cp_async16(void* d,const void* s){uint a=(uint)__cvta_generic_to_shared(d);asm volatile("cp.async.cg.shared.global [%0],[%1],16;"::"r"(a),"l"(s));}
__device__ __forceinline__ uint bfp(float x0,float x1){uint r;asm("cvt.rn.bf16x2.f32 %0,%1,%2;":"=r"(r):"f"(x1),"f"(x0));return r;}
__device__ __forceinline__ void mma16(float* c,uint a0,uint a1,uint a2,uint a3,uint b0,uint b1){
    asm("mma.sync.aligned.m16n8k16.row.col.f32.bf16.bf16.f32 {%0,%1,%2,%3},{%4,%5,%6,%7},{%8,%9},{%0,%1,%2,%3};"
        : "+f"(c[0]),"+f"(c[1]),"+f"(c[2]),"+f"(c[3])
        : "r"(a0),"r"(a1),"r"(a2),"r"(a3),"r"(b0),"r"(b1));}

// logits x[16,512]@conv^T -> redb bf16 [4][16][72]
__device__ __forceinline__ void phase2(const float* xb, char* smraw, int warp, int lane){
    const int grp=lane>>2, tig=lane&3;
    const int kt=warp>>3, cg=warp&7;
    float p0[4]={0.f,0.f,0.f,0.f}, p1[4]={0.f,0.f,0.f,0.f};
    const __nv_bfloat16* brow=(const __nv_bfloat16*)(smraw+CONV_OFF)+(cg*8+grp)*CPB+kt*128;
    #pragma unroll
    for(int s=0;s<4;s++){
        int c0=kt*128+s*16+2*tig, c1=c0+64;
        uint a0=bfp(xb[grp*XS+c0],      xb[grp*XS+c0+1]);
        uint a1=bfp(xb[(grp+8)*XS+c0],  xb[(grp+8)*XS+c0+1]);
        uint a2=bfp(xb[grp*XS+c0+8],    xb[grp*XS+c0+9]);
        uint a3=bfp(xb[(grp+8)*XS+c0+8],xb[(grp+8)*XS+c0+9]);
        uint b0=*(const uint*)(brow+s*16+2*tig);
        uint b1=*(const uint*)(brow+s*16+2*tig+8);
        mma16(p0,a0,a1,a2,a3,b0,b1);
        uint d0=bfp(xb[grp*XS+c1],      xb[grp*XS+c1+1]);
        uint d1=bfp(xb[(grp+8)*XS+c1],  xb[(grp+8)*XS+c1+1]);
        uint d2=bfp(xb[grp*XS+c1+8],    xb[grp*XS+c1+9]);
        uint d3=bfp(xb[(grp+8)*XS+c1+8],xb[(grp+8)*XS+c1+9]);
        uint e0=*(const uint*)(brow+(s+4)*16+2*tig);
        uint e1=*(const uint*)(brow+(s+4)*16+2*tig+8);
        mma16(p1,d0,d1,d2,d3,e0,e1);
    }
    uint* rb=(uint*)(smraw+REDB_OFF);
    int base=kt*576+cg*4+tig;
    rb[base+grp*36]    =bfp(p0[0]+p1[0], p0[1]+p1[1]);
    rb[base+(grp+8)*36]=bfp(p0[2]+p1[2], p0[3]+p1[3]);
}

// f32 x -> bf16 xT[c][t], one column per thread (tcol 0..511)
__device__ __forceinline__ void xt_convert(const float* xf, uint* xt, int tcol){
    const float* s=xf+tcol;
    uint u[8];
    #pragma unroll
    for(int j=0;j<8;j++) u[j]=bfp(s[(2*j)*XS], s[(2*j+1)*XS]);
    *(uint4*)(xt+tcol*XTW)  =make_uint4(u[0],u[1],u[2],u[3]);
    *(uint4*)(xt+tcol*XTW+4)=make_uint4(u[4],u[5],u[6],u[7]);
}

__device__ __forceinline__ void rownorm(const float* xf, float* inv_s, int row, int lane){
    const float* rp=xf+row*XS+4*lane;
    float ss=0.f;
    #pragma unroll
    for(int q=0;q<4;q++){float4 v=*(const float4*)(rp+q*128);ss+=v.x*v.x+v.y*v.y+v.z*v.z+v.w*v.w;}
    #pragma unroll
    for(int o=16;o;o>>=1) ss+=__shfl_xor_sync(0xffffffffu,ss,o);
    if(lane==0) inv_s[row]=1.0f/fmaxf(sqrtf(ss),1e-12f);
}

__global__ void __launch_bounds__(NT,1)
netvlad_kernel(const float* __restrict__ gin, const float* __restrict__ candA,
               const float* __restrict__ candB, const float* __restrict__ gfcw,
               const float* __restrict__ gfcb, float* __restrict__ gout)
{
    extern __shared__ __align__(1024) char smraw[];
    float* inv_s =(float*)(smraw+INV_OFF);
    float* asum_s=(float*)(smraw+ASUM_OFF);
    float* knorm =(float*)(smraw+KN_OFF);
    float* misc  =(float*)(smraw+MISC_OFF);
    float* wred  =(float*)(smraw+WRED_OFF);
    const int tid=threadIdx.x, lane=tid&31, warp=tid>>5, b=blockIdx.x;

    if (warp==0){
        float s=fabsf(candA[lane])+fabsf(candA[lane+32])+fabsf(candA[lane+64])+fabsf(candA[lane+96]);
        #pragma unroll
        for(int o=16;o;o>>=1) s+=__shfl_xor_sync(0xffffffffu,s,o);
        if(lane==0) misc[7]=s;
    }
    if (tid<Kk){asum_s[tid]=0.f; knorm[tid]=0.f;}
    if (tid<8) wred[tid]=0.f;
    __syncthreads();
    const bool aIsConv=(misc[7]<25.6f);
    const float* gconv=aIsConv?candA:candB;
    const float* gcent=aIsConv?candB:candA;
    __syncthreads();

    {   __nv_bfloat16* cb=(__nv_bfloat16*)(smraw+CONV_OFF);
        for(int idx=tid;idx<Kk*Cc;idx+=NT){int k=idx>>9,c=idx&511;cb[k*CPB+c]=__float2bfloat16(gconv[idx]);}
    }
    const float* inb=gin+(size_t)b*(Tt*Cc);
    const int lrow=tid>>6, lcol=(tid&63)*8;
    float* xf=(float*)(smraw+XF_OFF);
    uint*  xt=(uint*)(smraw+XT_OFF);

    // prologue: cp chunk0->buf0, chunk1->buf1
    {
        float* d0=xf+lrow*XS+lcol; const float* s0=inb+lrow*Cc+lcol;
        cp_async16(d0,s0); cp_async16(d0+4,s0+4);
        asm volatile("cp.async.commit_group;");
        float* d1=xf+TB*XS+lrow*XS+lcol; const float* s1=inb+TB*Cc+lrow*Cc+lcol;
        cp_async16(d1,s1); cp_async16(d1+4,s1+4);
        asm volatile("cp.async.commit_group;");
        asm volatile("cp.async.wait_group 1;");
    }
    const int grp=lane>>2, tig=lane&3;
    const int kt=warp>>3, cg=warp&7;
    float acc[8][4];
    #pragma unroll
    for(int i=0;i<8;i++){acc[i][0]=0.f;acc[i][1]=0.f;acc[i][2]=0.f;acc[i][3]=0.f;}
    __syncthreads();
    // prologue region: phase2(0) [all] + convert(0)[thr<512] + norm(0)[warps16-31]
    phase2(xf, smraw, warp, lane);
    if (tid<512) xt_convert(xf, xt, tid);
    else rownorm(xf, inv_s, warp-16, lane);
    __syncthreads();

    for (int ch=0; ch<NCHUNK; ch++){
        const int cur=ch&1, nxt=(ch+1)&1;
        // ---- R1: softmax(ch) [w0-15] ; convert+norm(ch+1) [w16-31] ----
        asm volatile("cp.async.wait_group 0;");
        if (warp<16){
            const int t=warp;
            const __nv_bfloat16* rbh=(const __nv_bfloat16*)(smraw+REDB_OFF);
            float inv=inv_s[t];
            float lg0=0.f,lg1=0.f;
            #pragma unroll
            for(int s=0;s<4;s++){
                lg0+=__bfloat162float(rbh[s*1152+t*72+lane]);
                lg1+=__bfloat162float(rbh[s*1152+t*72+lane+32]);
            }
            lg0*=inv; lg1*=inv;
            float m=fmaxf(lg0,lg1);
            #pragma unroll
            for(int o=16;o;o>>=1) m=fmaxf(m,__shfl_xor_sync(0xffffffffu,m,o));
            float e0=__expf(lg0-m),e1=__expf(lg1-m),s2=e0+e1;
            #pragma unroll
            for(int o=16;o;o>>=1) s2+=__shfl_xor_sync(0xffffffffu,s2,o);
            float a0=e0/s2,a1=e1/s2;
            __nv_bfloat16* aT=(__nv_bfloat16*)(smraw+AT_OFF);
            aT[lane*24+t]     =__float2bfloat16(a0*inv);   // a' = a/||x||
            aT[(lane+32)*24+t]=__float2bfloat16(a1*inv);
            atomicAdd(&asum_s[lane],a0); atomicAdd(&asum_s[lane+32],a1);
        } else if (ch+1<NCHUNK){
            xt_convert(xf+nxt*(TB*XS), xt+nxt*(512*XTW), tid-512);
            rownorm(xf+nxt*(TB*XS), inv_s, warp-16, lane);
        }
        __syncthreads();
        // ---- R2: cp(ch+2) + phase2(ch+1) + VLAD(ch) ----
        if (ch+2<NCHUNK){
            float* d=xf+((ch+2)&1)*(TB*XS)+lrow*XS+lcol;
            const float* s=inb+(ch+2)*(TB*Cc)+lrow*Cc+lcol;
            cp_async16(d,s); cp_async16(d+4,s+4);
            asm volatile("cp.async.commit_group;");
        }
        if (ch+1<NCHUNK) phase2(xf+nxt*(TB*XS), smraw, warp, lane);
        {
            const uint* aT32=(const uint*)(smraw+AT_OFF);
            const uint* xtc=xt+cur*(512*XTW);
            const int r=kt*16+grp;
            uint fa0=aT32[r*XTW+tig],     fa1=aT32[(r+8)*XTW+tig];
            uint fa2=aT32[r*XTW+tig+4],   fa3=aT32[(r+8)*XTW+tig+4];
            const int cb=cg*64+grp;
            #pragma unroll
            for(int i=0;i<8;i++){
                int c=cb+i*8;
                uint fb0=xtc[c*XTW+tig], fb1=xtc[c*XTW+tig+4];
                mma16(acc[i],fa0,fa1,fa2,fa3,fb0,fb1);
            }
        }
        __syncthreads();
    }

    // ===== epilogue (verified) =====
    float* vlad=(float*)smraw;   // overlay xf+xT+conv, stride VS
    {
        int r0=kt*16+grp, r1=r0+8;
        float a0s=asum_s[r0], a1s=asum_s[r1];
        float pk0=0.f, pk1=0.f;
        #pragma unroll
        for(int i=0;i<8;i++){
            int c=cg*64+i*8+2*tig;
            float2 c0=*(const float2*)(gcent+(size_t)r0*Cc+c);
            float2 c1=*(const float2*)(gcent+(size_t)r1*Cc+c);
            float v00=acc[i][0]-a0s*c0.x, v01=acc[i][1]-a0s*c0.y;
            float v10=acc[i][2]-a1s*c1.x, v11=acc[i][3]-a1s*c1.y;
            vlad[r0*VS+c]=v00; vlad[r0*VS+c+1]=v01;
            vlad[r1*VS+c]=v10; vlad[r1*VS+c+1]=v11;
            pk0+=v00*v00+v01*v01; pk1+=v10*v10+v11*v11;
        }
        pk0+=__shfl_xor_sync(0xffffffffu,pk0,1); pk0+=__shfl_xor_sync(0xffffffffu,pk0,2);
        pk1+=__shfl_xor_sync(0xffffffffu,pk1,1); pk1+=__shfl_xor_sync(0xffffffffu,pk1,2);
        if(tig==0){atomicAdd(&knorm[r0],pk0); atomicAdd(&knorm[r1],pk1);}
    }
    __syncthreads();
    if (warp==0){
        float c0=0.f;
        #pragma unroll
        for(int r=0;r<2;r++){float nn=knorm[lane+32*r];float iv=1.0f/fmaxf(sqrtf(nn),1e-12f);c0+=nn*iv*iv;}
        #pragma unroll
        for(int o=16;o;o>>=1) c0+=__shfl_xor_sync(0xffffffffu,c0,o);
        if(lane==0) misc[0]=1.0f/fmaxf(sqrtf(c0),1e-12f);
    }
    __syncthreads();
    {
        float invtot=misc[0];
        int k=tid>>4;
        float sc=(1.0f/fmaxf(sqrtf(knorm[k]),1e-12f))*invtot;
        int off=(tid&15)*32;
        float fo[NCn]={0.f,0.f,0.f,0.f};
        #pragma unroll 4
        for(int o=0;o<32;o++){
            int j=off+((o+lane)&31);
            float v=vlad[k*VS+j]*sc;
            #pragma unroll
            for(int n=0;n<NCn;n++) fo[n]+=v*gfcw[(size_t)n*(Kk*Cc)+k*Cc+j];
        }
        #pragma unroll
        for(int n=0;n<NCn;n++){
            float v=fo[n];
            #pragma unroll
            for(int o=16;o;o>>=1) v+=__shfl_xor_sync(0xffffffffu,v,o);
            if(lane==0) atomicAdd(&wred[n],v);
        }
    }
    __syncthreads();
    if (tid<NCn){
        float z=gfcb[tid]+wred[tid];
        gout[b*NCn+tid]=1.0f/(1.0f+__expf(-z));
    }
}

extern "C" void kernel_launch(void* const* d_in, const int* in_sizes, int n_in,
                              void* d_out, int out_size) {
    const float *gin=nullptr,*gfcw=nullptr,*gfcb=nullptr,*cand[2]={nullptr,nullptr};
    if (n_in>=5){
        int used[32]; for(int i=0;i<n_in&&i<32;i++) used[i]=0;
        int imax=-1; for(int i=0;i<n_in&&i<32;i++) if(!used[i]&&(imax<0||in_sizes[i]>in_sizes[imax])) imax=i;
        used[imax]=1; gin=(const float*)d_in[imax];
        int imin=-1; for(int i=0;i<n_in&&i<32;i++) if(!used[i]&&(imin<0||in_sizes[i]<in_sizes[imin])) imin=i;
        used[imin]=1; gfcb=(const float*)d_in[imin];
        int iw=-1; for(int i=0;i<n_in&&i<32;i++) if(!used[i]&&(iw<0||in_sizes[i]>in_sizes[iw])) iw=i;
        used[iw]=1; gfcw=(const float*)d_in[iw];
        int nc=0; for(int i=0;i<n_in&&i<32&&nc<2;i++) if(!used[i]){cand[nc++]=(const float*)d_in[i];used[i]=1;}
        if (nc<2 || in_sizes[imax]==in_sizes[iw] || in_sizes[iw]<=in_sizes[imin]){
            gin=(const float*)d_in[0]; cand[0]=(const float*)d_in[1]; cand[1]=(const float*)d_in[2];
            gfcw=(const float*)d_in[3]; gfcb=(const float*)d_in[4];
        }
    }
    cudaFuncSetAttribute(netvlad_kernel, cudaFuncAttributeMaxDynamicSharedMemorySize, SMEM_TOTAL);
    netvlad_kernel<<<Bb, NT, SMEM_TOTAL>>>(gin, cand[0], cand[1], gfcw, gfcb, (float*)d_out);
}

// round 16
// speedup vs baseline: 1.3851x; 1.1991x over previous
#include <cuda_runtime.h>
#include <cuda_bf16.h>

#define Bb 256
#define Tt 240
#define Cc 512
#define Kk 64
#define NCn 4
#define TB 16
#define NCHUNK 15
#define NT 1024
#define XS 520            // f32 x row stride (words)
#define XTW 12            // xT row stride (uints)

// smem byte offsets
#define XF_OFF   0                  // f32 [16][520] = 33280 (single buffer)
#define XT_OFF   33280              // bf16 xT [2][512][24] = 49152 -> 82432
#define REDB_OFF 82432              // bf16 [4][16][72] = 9216 -> 91648
#define AT_OFF   91648              // bf16 [64][24] = 3072 -> 94720
#define INV_OFF  94720              // f32 [2][16] = 128 -> 94848
#define ASUM_OFF 94848              // 256 -> 95104
#define KN_OFF   95104              // 256 -> 95360
#define MISC_OFF 95360              // 32 -> 95392
#define WRED_OFF 95392              // 32 -> 95424
#define SMEM_TOTAL 95424

typedef unsigned int uint;

__device__ __forceinline__ void cp_async16(void* d,const void* s){uint a=(uint)__cvta_generic_to_shared(d);asm volatile("cp.async.cg.shared.global [%0],[%1],16;"::"r"(a),"l"(s));}
__device__ __forceinline__ uint bfp(float x0,float x1){uint r;asm("cvt.rn.bf16x2.f32 %0,%1,%2;":"=r"(r):"f"(x1),"f"(x0));return r;}
__device__ __forceinline__ void mma16(float* c,uint a0,uint a1,uint a2,uint a3,uint b0,uint b1){
    asm("mma.sync.aligned.m16n8k16.row.col.f32.bf16.bf16.f32 {%0,%1,%2,%3},{%4,%5,%6,%7},{%8,%9},{%0,%1,%2,%3};"
        : "+f"(c[0]),"+f"(c[1]),"+f"(c[2]),"+f"(c[3])
        : "r"(a0),"r"(a1),"r"(a2),"r"(a3),"r"(b0),"r"(b1));}

// logits x[16,512]@conv^T -> redb bf16; conv frags in registers
__device__ __forceinline__ void phase2(const float* xb, char* smraw, const uint (&cb0)[8], const uint (&cb1)[8], int warp, int lane){
    const int grp=lane>>2, tig=lane&3;
    const int kt=warp>>3, cg=warp&7;
    float p0[4]={0.f,0.f,0.f,0.f}, p1[4]={0.f,0.f,0.f,0.f};
    #pragma unroll
    for(int s=0;s<8;s++){
        int c0=kt*128+s*16+2*tig;
        uint a0=bfp(xb[grp*XS+c0],      xb[grp*XS+c0+1]);
        uint a1=bfp(xb[(grp+8)*XS+c0],  xb[(grp+8)*XS+c0+1]);
        uint a2=bfp(xb[grp*XS+c0+8],    xb[grp*XS+c0+9]);
        uint a3=bfp(xb[(grp+8)*XS+c0+8],xb[(grp+8)*XS+c0+9]);
        if(s&1) mma16(p1,a0,a1,a2,a3,cb0[s],cb1[s]);
        else    mma16(p0,a0,a1,a2,a3,cb0[s],cb1[s]);
    }
    uint* rb=(uint*)(smraw+REDB_OFF);
    int base=kt*576+cg*4+tig;
    rb[base+grp*36]    =bfp(p0[0]+p1[0], p0[1]+p1[1]);
    rb[base+(grp+8)*36]=bfp(p0[2]+p1[2], p0[3]+p1[3]);
}

// f32 x -> bf16 xT[c][t] (one column per thread, tcol 0..511)
__device__ __forceinline__ void xt_convert(const float* xf, uint* xt, int tcol){
    const float* s=xf+tcol;
    uint u[8];
    #pragma unroll
    for(int j=0;j<8;j++) u[j]=bfp(s[(2*j)*XS], s[(2*j+1)*XS]);
    *(uint4*)(xt+tcol*XTW)  =make_uint4(u[0],u[1],u[2],u[3]);
    *(uint4*)(xt+tcol*XTW+4)=make_uint4(u[4],u[5],u[6],u[7]);
}

__device__ __forceinline__ void rownorm(const float* xf, float* inv_s, int row, int lane){
    const float* rp=xf+row*XS+4*lane;
    float ss=0.f;
    #pragma unroll
    for(int q=0;q<4;q++){float4 v=*(const float4*)(rp+q*128);ss+=v.x*v.x+v.y*v.y+v.z*v.z+v.w*v.w;}
    #pragma unroll
    for(int o=16;o;o>>=1) ss+=__shfl_xor_sync(0xffffffffu,ss,o);
    if(lane==0) inv_s[row]=1.0f/fmaxf(sqrtf(ss),1e-12f);
}

__global__ void __launch_bounds__(NT,2)
netvlad_kernel(const float* __restrict__ gin, const float* __restrict__ candA,
               const float* __restrict__ candB, const float* __restrict__ gfcw,
               const float* __restrict__ gfcb, float* __restrict__ gout)
{
    extern __shared__ __align__(1024) char smraw[];
    float* inv_s =(float*)(smraw+INV_OFF);
    float* asum_s=(float*)(smraw+ASUM_OFF);
    float* knorm =(float*)(smraw+KN_OFF);
    float* misc  =(float*)(smraw+MISC_OFF);
    float* wred  =(float*)(smraw+WRED_OFF);
    const int tid=threadIdx.x, lane=tid&31, warp=tid>>5, b=blockIdx.x;

    if (warp==0){
        float s=fabsf(candA[lane])+fabsf(candA[lane+32])+fabsf(candA[lane+64])+fabsf(candA[lane+96]);
        #pragma unroll
        for(int o=16;o;o>>=1) s+=__shfl_xor_sync(0xffffffffu,s,o);
        if(lane==0) misc[7]=s;
    }
    if (tid<Kk){asum_s[tid]=0.f; knorm[tid]=0.f;}
    if (tid<8) wred[tid]=0.f;
    __syncthreads();
    const bool aIsConv=(misc[7]<25.6f);
    const float* gconv=aIsConv?candA:candB;
    const float* gcent=aIsConv?candB:candA;
    __syncthreads();

    const int grp=lane>>2, tig=lane&3;
    const int kt=warp>>3, cg=warp&7;

    // conv fragments -> registers (fixed per warp)
    uint cb0[8], cb1[8];
    {
        const float* wr=gconv+(size_t)(cg*8+grp)*Cc+kt*128+2*tig;
        #pragma unroll
        for(int s=0;s<8;s++){
            float2 w0=*(const float2*)(wr+s*16);
            float2 w1=*(const float2*)(wr+s*16+8);
            cb0[s]=bfp(w0.x,w0.y); cb1[s]=bfp(w1.x,w1.y);
        }
    }

    const float* inb=gin+(size_t)b*(Tt*Cc);
    const int lrow=tid>>6, lcol=(tid&63)*8;
    float* xf=(float*)(smraw+XF_OFF);
    uint*  xt=(uint*)(smraw+XT_OFF);

    float acc[8][4];
    #pragma unroll
    for(int i=0;i<8;i++){acc[i][0]=0.f;acc[i][1]=0.f;acc[i][2]=0.f;acc[i][3]=0.f;}

    // prologue: cp(0); wait; phase2(0) + convert(0)+norm(0); cp(1)
    {
        float* d=xf+lrow*XS+lcol; const float* s=inb+lrow*Cc+lcol;
        cp_async16(d,s); cp_async16(d+4,s+4);
        asm volatile("cp.async.commit_group;");
        asm volatile("cp.async.wait_group 0;");
    }
    __syncthreads();
    phase2(xf, smraw, cb0, cb1, warp, lane);
    if (warp>=16){ xt_convert(xf, xt, tid-512); rownorm(xf, inv_s, warp-16, lane); }
    __syncthreads();
    {
        float* d=xf+lrow*XS+lcol; const float* s=inb+TB*Cc+lrow*Cc+lcol;
        cp_async16(d,s); cp_async16(d+4,s+4);
        asm volatile("cp.async.commit_group;");
    }

    for (int ch=0; ch<NCHUNK; ch++){
        // ---- R1: softmax(ch) [w0-15] ----
        if (warp<16){
            const int t=warp;
            const __nv_bfloat16* rbh=(const __nv_bfloat16*)(smraw+REDB_OFF);
            float inv=inv_s[(ch&1)*16+t];
            float lg0=0.f,lg1=0.f;
            #pragma unroll
            for(int s=0;s<4;s++){
                lg0+=__bfloat162float(rbh[s*1152+t*72+lane]);
                lg1+=__bfloat162float(rbh[s*1152+t*72+lane+32]);
            }
            lg0*=inv; lg1*=inv;
            float m=fmaxf(lg0,lg1);
            #pragma unroll
            for(int o=16;o;o>>=1) m=fmaxf(m,__shfl_xor_sync(0xffffffffu,m,o));
            float e0=__expf(lg0-m),e1=__expf(lg1-m),s2=e0+e1;
            #pragma unroll
            for(int o=16;o;o>>=1) s2+=__shfl_xor_sync(0xffffffffu,s2,o);
            float a0=e0/s2,a1=e1/s2;
            __nv_bfloat16* aT=(__nv_bfloat16*)(smraw+AT_OFF);
            aT[lane*24+t]     =__float2bfloat16(a0*inv);
            aT[(lane+32)*24+t]=__float2bfloat16(a1*inv);
            atomicAdd(&asum_s[lane],a0); atomicAdd(&asum_s[lane+32],a1);
        }
        __syncthreads();
        // ---- R2: wait cp(ch+1); phase2(ch+1) + VLAD(ch) + convert/norm(ch+1) ----
        asm volatile("cp.async.wait_group 0;");
        if (ch+1<NCHUNK) phase2(xf, smraw, cb0, cb1, warp, lane);
        {
            const uint* aT32=(const uint*)(smraw+AT_OFF);
            const uint* xtc=xt+(ch&1)*(512*XTW);
            const int r=kt*16+grp;
            uint fa0=aT32[r*XTW+tig],   fa1=aT32[(r+8)*XTW+tig];
            uint fa2=aT32[r*XTW+tig+4], fa3=aT32[(r+8)*XTW+tig+4];
            const int cb=cg*64+grp;
            #pragma unroll
            for(int i=0;i<8;i++){
                int c=cb+i*8;
                uint fb0=xtc[c*XTW+tig], fb1=xtc[c*XTW+tig+4];
                mma16(acc[i],fa0,fa1,fa2,fa3,fb0,fb1);
            }
        }
        if (ch+1<NCHUNK && warp>=16){
            xt_convert(xf, xt+((ch+1)&1)*(512*XTW), tid-512);
            rownorm(xf, inv_s+((ch+1)&1)*16, warp-16, lane);
        }
        __syncthreads();
        if (ch+2<NCHUNK){
            float* d=xf+lrow*XS+lcol;
            const float* s=inb+(ch+2)*(TB*Cc)+lrow*Cc+lcol;
            cp_async16(d,s); cp_async16(d+4,s+4);
            asm volatile("cp.async.commit_group;");
        }
    }

    // ===== epilogue: register-resident =====
    {
        int r0=kt*16+grp, r1=r0+8;
        float a0s=asum_s[r0], a1s=asum_s[r1];
        float pk0=0.f, pk1=0.f;
        #pragma unroll
        for(int i=0;i<8;i++){
            int c=cg*64+i*8+2*tig;
            float2 c0=*(const float2*)(gcent+(size_t)r0*Cc+c);
            float2 c1=*(const float2*)(gcent+(size_t)r1*Cc+c);
            acc[i][0]-=a0s*c0.x; acc[i][1]-=a0s*c0.y;
            acc[i][2]-=a1s*c1.x; acc[i][3]-=a1s*c1.y;
            pk0+=acc[i][0]*acc[i][0]+acc[i][1]*acc[i][1];
            pk1+=acc[i][2]*acc[i][2]+acc[i][3]*acc[i][3];
        }
        pk0+=__shfl_xor_sync(0xffffffffu,pk0,1); pk0+=__shfl_xor_sync(0xffffffffu,pk0,2);
        pk1+=__shfl_xor_sync(0xffffffffu,pk1,1); pk1+=__shfl_xor_sync(0xffffffffu,pk1,2);
        if(tig==0){atomicAdd(&knorm[r0],pk0); atomicAdd(&knorm[r1],pk1);}
    }
    __syncthreads();
    if (warp==0){
        float c0=0.f;
        #pragma unroll
        for(int r=0;r<2;r++){float nn=knorm[lane+32*r];float iv=1.0f/fmaxf(sqrtf(nn),1e-12f);c0+=nn*iv*iv;}
        #pragma unroll
        for(int o=16;o;o>>=1) c0+=__shfl_xor_sync(0xffffffffu,c0,o);
        if(lane==0) misc[0]=1.0f/fmaxf(sqrtf(c0),1e-12f);
    }
    __syncthreads();
    {
        float invtot=misc[0];
        int r0=kt*16+grp, r1=r0+8;
        float sc0=(1.0f/fmaxf(sqrtf(knorm[r0]),1e-12f))*invtot;
        float sc1=(1.0f/fmaxf(sqrtf(knorm[r1]),1e-12f))*invtot;
        float fo[NCn]={0.f,0.f,0.f,0.f};
        #pragma unroll
        for(int i=0;i<8;i++){
            int c=cg*64+i*8+2*tig;
            #pragma unroll
            for(int n=0;n<NCn;n++){
                const float* fw=gfcw+(size_t)n*(Kk*Cc);
                float2 w0=*(const float2*)(fw+(size_t)r0*Cc+c);
                float2 w1=*(const float2*)(fw+(size_t)r1*Cc+c);
                fo[n]+=sc0*(acc[i][0]*w0.x+acc[i][1]*w0.y)
                     +sc1*(acc[i][2]*w1.x+acc[i][3]*w1.y);
            }
        }
        #pragma unroll
        for(int n=0;n<NCn;n++){
            float v=fo[n];
            #pragma unroll
            for(int o=16;o;o>>=1) v+=__shfl_xor_sync(0xffffffffu,v,o);
            if(lane==0) atomicAdd(&wred[n],v);
        }
    }
    __syncthreads();
    if (tid<NCn){
        float z=gfcb[tid]+wred[tid];
        gout[b*NCn+tid]=1.0f/(1.0f+__expf(-z));
    }
}

extern "C" void kernel_launch(void* const* d_in, const int* in_sizes, int n_in,
                              void* d_out, int out_size) {
    const float *gin=nullptr,*gfcw=nullptr,*gfcb=nullptr,*cand[2]={nullptr,nullptr};
    if (n_in>=5){
        int used[32]; for(int i=0;i<n_in&&i<32;i++) used[i]=0;
        int imax=-1; for(int i=0;i<n_in&&i<32;i++) if(!used[i]&&(imax<0||in_sizes[i]>in_sizes[imax])) imax=i;
        used[imax]=1; gin=(const float*)d_in[imax];
        int imin=-1; for(int i=0;i<n_in&&i<32;i++) if(!used[i]&&(imin<0||in_sizes[i]<in_sizes[imin])) imin=i;
        used[imin]=1; gfcb=(const float*)d_in[imin];
        int iw=-1; for(int i=0;i<n_in&&i<32;i++) if(!used[i]&&(iw<0||in_sizes[i]>in_sizes[iw])) iw=i;
        used[iw]=1; gfcw=(const float*)d_in[iw];
        int nc=0; for(int i=0;i<n_in&&i<32&&nc<2;i++) if(!used[i]){cand[nc++]=(const float*)d_in[i];used[i]=1;}
        if (nc<2 || in_sizes[imax]==in_sizes[iw] || in_sizes[iw]<=in_sizes[imin]){
            gin=(const float*)d_in[0]; cand[0]=(const float*)d_in[1]; cand[1]=(const float*)d_in[2];
            gfcw=(const float*)d_in[3]; gfcb=(const float*)d_in[4];
        }
    }
    cudaFuncSetAttribute(netvlad_kernel, cudaFuncAttributeMaxDynamicSharedMemorySize, SMEM_TOTAL);
    netvlad_kernel<<<Bb, NT, SMEM_TOTAL>>>(gin, cand[0], cand[1], gfcw, gfcb, (float*)d_out);
}